// round 13
// baseline (speedup 1.0000x reference)
#include <cuda_runtime.h>
#include <math.h>

// One 64x64 matrix per WARP. Francis double-shift QR, fully warp-synchronous:
// rotation + 4x3 bulge window computed redundantly in every lane (registers),
// one __syncwarp per chase step, ballot-based parallel deflation.
// F = f(T) block-Parlett, M = Q F Q^T, out = 0.5(M + M^T).

#define N 64
#define LDH 65
#define ULPF 1.1920929e-7f
#define MAXSW 960
#define FULLM 0xffffffffu

__device__ __forceinline__ float guard(float d){ return (fabsf(d)<1e-25f)?copysignf(1e-25f,d):d; }
__device__ __forceinline__ void gen3(float x,float y,float z,float&tau,float&v1,float&v2,float&beta){
    float ssq=y*y+z*z;
    if(ssq==0.f){tau=0.f;v1=0.f;v2=0.f;beta=x;return;}
    float nrm=sqrtf(x*x+ssq);
    beta=(x>=0.f)?-nrm:nrm;
    tau=(beta-x)/beta; float inv=1.f/(x-beta);
    v1=y*inv; v2=z*inv;
}
__device__ __forceinline__ void gen2(float x,float y,float&tau,float&v1,float&beta){
    if(y==0.f){tau=0.f;v1=0.f;beta=x;return;}
    float nrm=sqrtf(x*x+y*y);
    beta=(x>=0.f)?-nrm:nrm;
    tau=(beta-x)/beta; v1=y/(x-beta);
}

__global__ void __launch_bounds__(32, 6)
spd_project_kernel(const float* __restrict__ X, float* __restrict__ OUT, int nmat)
{
    extern __shared__ float sm[];
    float* H = sm;               // Hessenberg -> T; F packed strictly-lower; later M
    float* Q = sm + N * LDH;

    __shared__ float s_v[N];
    __shared__ int   s_bs[N], s_fbi[N], s_cb[N], s_bsz[N];
    __shared__ float s_f2[N][4];

    const int lane = threadIdx.x;
    const int g = blockIdx.x;
    if (g >= nmat) return;
    const float* A = X + (size_t)g * (N * N);
    float* Og = OUT + (size_t)g * (N * N);

    for (int idx = lane; idx < N * N; idx += 32) {
        int i = idx >> 6, j = idx & 63;
        H[i * LDH + j] = A[idx];
        Q[i * LDH + j] = (i == j) ? 1.f : 0.f;
    }
    __syncwarp(FULLM);

    // ---------------- Hessenberg ----------------
    for (int k = 0; k < N - 2; k++) {
        const int m = N - 1 - k;
        float t = 0.f;
        { int r1 = k + 2 + lane; if (r1 < N) { float h = H[r1 * LDH + k]; t = h * h; } }
        { int r2 = k + 34 + lane; if (r2 < N) { float h = H[r2 * LDH + k]; t += h * h; } }
        #pragma unroll
        for (int off = 16; off >= 1; off >>= 1) t += __shfl_xor_sync(FULLM, t, off);
        const float sigma = t;
        if (sigma > 0.f) {   // uniform
            float x0 = H[(k + 1) * LDH + k];
            float mu = sqrtf(x0 * x0 + sigma);
            float v0 = (x0 <= 0.f) ? (x0 - mu) : (-sigma / (x0 + mu));
            float beta = 2.f * v0 * v0 / (sigma + v0 * v0);
            float iv0 = 1.f / v0;
            #pragma unroll
            for (int rep = 0; rep < 2; rep++) {
                int r = lane + rep * 32;
                if (r < m) s_v[r] = (r == 0) ? 1.f : H[(k + 1 + r) * LDH + k] * iv0;
            }
            __syncwarp(FULLM);
            #pragma unroll
            for (int rep = 0; rep < 2; rep++) {     // left on H cols
                int j = k + lane + rep * 32;
                if (j < N) {
                    float w = 0.f;
                    for (int i = 0; i < m; i++) w += s_v[i] * H[(k + 1 + i) * LDH + j];
                    w *= beta;
                    for (int i = 0; i < m; i++) H[(k + 1 + i) * LDH + j] -= s_v[i] * w;
                }
            }
            #pragma unroll
            for (int rep = 0; rep < 2; rep++) {     // right on Q rows
                int i = lane + rep * 32;
                float wq = 0.f;
                for (int l = 0; l < m; l++) wq += Q[i * LDH + k + 1 + l] * s_v[l];
                wq *= beta;
                for (int l = 0; l < m; l++) Q[i * LDH + k + 1 + l] -= wq * s_v[l];
            }
            __syncwarp(FULLM);
            #pragma unroll
            for (int rep = 0; rep < 2; rep++) {     // right on H rows
                int i = lane + rep * 32;
                float w = 0.f;
                for (int l = 0; l < m; l++) w += H[i * LDH + k + 1 + l] * s_v[l];
                w *= beta;
                for (int l = 0; l < m; l++) H[i * LDH + k + 1 + l] -= w * s_v[l];
                if (i >= k + 2) H[i * LDH + k] = 0.f;
            }
            __syncwarp(FULLM);
        }
    }

    // ---------------- Francis double-shift QR (warp-synchronous) ----------------
    {
        int its = 0, tot = 0, hi = N - 1, prev_hi = -1;
        while (true) {
            // parallel deflation: lane tests subdiags m=lane (bit0=boundary) and m=lane+32
            bool z1 = true, z2;
            if (lane >= 1) {
                int m1 = lane;
                float sub = fabsf(H[m1 * LDH + m1 - 1]);
                float dd = fabsf(H[(m1 - 1) * LDH + m1 - 1]) + fabsf(H[m1 * LDH + m1]);
                z1 = (sub <= ULPF * dd + 1e-30f);
                if (z1) H[m1 * LDH + m1 - 1] = 0.f;
            }
            {
                int m2 = lane + 32;
                float sub = fabsf(H[m2 * LDH + m2 - 1]);
                float dd = fabsf(H[(m2 - 1) * LDH + m2 - 1]) + fabsf(H[m2 * LDH + m2]);
                z2 = (sub <= ULPF * dd + 1e-30f);
                if (z2) H[m2 * LDH + m2 - 1] = 0.f;
            }
            unsigned lowm  = __ballot_sync(FULLM, z1);
            unsigned highm = __ballot_sync(FULLM, z2);
            unsigned long long mask = ((unsigned long long)highm << 32) | (unsigned long long)lowm;
            __syncwarp(FULLM);   // zero-writes visible before any use of H
            // pop converged tail
            while (hi > 0) {
                if ((mask >> hi) & 1ull) hi -= 1;
                else if ((mask >> (hi - 1)) & 1ull) hi -= 2;
                else break;
            }
            if (hi != prev_hi) { its = 0; prev_hi = hi; }
            if (hi <= 0 || tot >= MAXSW) break;
            tot++; its++;
            unsigned long long lm = mask & ((hi >= 63) ? ~0ull : ((1ull << (hi + 1)) - 1ull));
            int lo = 63 - __clzll(lm);

            float t0, d0;
            if (its % 10 == 0) {
                float s2 = fabsf(H[hi * LDH + hi - 1]) + fabsf(H[(hi - 1) * LDH + hi - 2]);
                float h11 = 0.75f * s2 + H[hi * LDH + hi];
                t0 = 2.f * h11; d0 = h11 * h11 + 0.4375f * s2 * s2;
            } else {
                t0 = H[(hi - 1) * LDH + hi - 1] + H[hi * LDH + hi];
                d0 = H[(hi - 1) * LDH + hi - 1] * H[hi * LDH + hi]
                   - H[(hi - 1) * LDH + hi] * H[hi * LDH + hi - 1];
            }
            float h00 = H[lo * LDH + lo],       h01 = H[lo * LDH + lo + 1];
            float h10 = H[(lo + 1) * LDH + lo], h11v = H[(lo + 1) * LDH + lo + 1];
            float h21 = H[(lo + 2) * LDH + lo + 1];
            float tau, v1, v2, betac;
            gen3(h00*h00 + h01*h10 - t0*h00 + d0, h10*(h00 + h11v - t0), h21*h10, tau, v1, v2, betac);

            float w[4][3];                       // window, redundant in every lane
            #pragma unroll
            for (int r = 0; r < 3; r++)
                #pragma unroll
                for (int c = 0; c < 3; c++) w[r][c] = H[(lo + r) * LDH + lo + c];
            { bool r3 = (lo + 3 <= hi);
              #pragma unroll
              for (int c = 0; c < 3; c++) w[3][c] = r3 ? H[(lo + 3) * LDH + lo + c] : 0.f; }
            __syncwarp(FULLM);                   // control reads before chase writes

            for (int k = lo; k < hi; k++) {
                bool last = (k == hi - 1);
                float a1s = 0.f, a2s = 0.f;
                int jb = last ? (k + 2) : (k + 3);
                #pragma unroll
                for (int rep = 0; rep < 2; rep++) {          // left: rows k..k+2
                    int j = jb + lane + rep * 32;
                    if (j < N) {
                        float a0 = H[k * LDH + j], a1 = H[(k + 1) * LDH + j];
                        if (!last) {
                            float a2 = H[(k + 2) * LDH + j];
                            float s0 = tau * (a0 + v1 * a1 + v2 * a2);
                            H[k * LDH + j] = a0 - s0;
                            float n1 = a1 - v1 * s0, n2 = a2 - v2 * s0;
                            H[(k + 1) * LDH + j] = n1; H[(k + 2) * LDH + j] = n2;
                            if (rep == 0 && lane == 0) { a1s = n1; a2s = n2; }
                        } else {
                            float s0 = tau * (a0 + v1 * a1);
                            H[k * LDH + j] = a0 - s0; H[(k + 1) * LDH + j] = a1 - v1 * s0;
                        }
                    }
                }
                #pragma unroll
                for (int rep = 0; rep < 2; rep++) {          // right: rows < k
                    int i = lane + rep * 32;
                    if (i < k) {
                        float a0 = H[i * LDH + k], a1 = H[i * LDH + k + 1];
                        if (!last) {
                            float a2 = H[i * LDH + k + 2];
                            float s0 = tau * (a0 + v1 * a1 + v2 * a2);
                            H[i*LDH+k] = a0 - s0; H[i*LDH+k+1] = a1 - v1*s0; H[i*LDH+k+2] = a2 - v2*s0;
                        } else {
                            float s0 = tau * (a0 + v1 * a1);
                            H[i*LDH+k] = a0 - s0; H[i*LDH+k+1] = a1 - v1*s0;
                        }
                    }
                }
                #pragma unroll
                for (int rep = 0; rep < 2; rep++) {          // Q right: all rows
                    int i = lane + rep * 32;
                    float q0 = Q[i * LDH + k], q1 = Q[i * LDH + k + 1];
                    if (!last) {
                        float q2 = Q[i * LDH + k + 2];
                        float s0 = tau * (q0 + v1 * q1 + v2 * q2);
                        Q[i*LDH+k] = q0 - s0; Q[i*LDH+k+1] = q1 - v1*s0; Q[i*LDH+k+2] = q2 - v2*s0;
                    } else {
                        float s0 = tau * (q0 + v1 * q1);
                        Q[i*LDH+k] = q0 - s0; Q[i*LDH+k+1] = q1 - v1*s0;
                    }
                }
                if (!last) {
                    #pragma unroll
                    for (int c = 0; c < 3; c++) {            // window col applies
                        float s0 = tau * (w[0][c] + v1 * w[1][c] + v2 * w[2][c]);
                        w[0][c] -= s0; w[1][c] -= v1 * s0; w[2][c] -= v2 * s0;
                    }
                    #pragma unroll
                    for (int r = 0; r < 4; r++) {            // window row applies
                        float s0 = tau * (w[r][0] + v1 * w[r][1] + v2 * w[r][2]);
                        w[r][0] -= s0; w[r][1] -= v1 * s0; w[r][2] -= v2 * s0;
                    }
                    if (lane == 0) {                         // row k exits window
                        if (k > lo) H[k * LDH + k - 1] = betac;
                        H[k*LDH+k] = w[0][0]; H[k*LDH+k+1] = w[0][1]; H[k*LDH+k+2] = w[0][2];
                    }
                    float tn, v1n, v2n = 0.f, bn;
                    if (k + 1 == hi - 1) gen2(w[1][0], w[2][0], tn, v1n, bn);
                    else                 gen3(w[1][0], w[2][0], w[3][0], tn, v1n, v2n, bn);
                    #pragma unroll
                    for (int r = 0; r < 3; r++) { w[r][0] = w[r+1][1]; w[r][1] = w[r+1][2]; }
                    w[3][0] = 0.f; w[3][1] = 0.f;
                    // fresh col k+3: rows k+1,k+2 via shfl from lane0; k+3,k+4 race-free smem
                    w[0][2] = __shfl_sync(FULLM, a1s, 0);
                    w[1][2] = __shfl_sync(FULLM, a2s, 0);
                    w[2][2] = (k + 3 <= hi) ? H[(k + 3) * LDH + (k + 3)] : 0.f;
                    w[3][2] = (k + 4 <= hi) ? H[(k + 4) * LDH + (k + 3)] : 0.f;
                    tau = tn; v1 = v1n; v2 = v2n; betac = bn;
                } else {
                    float a0 = w[0][0], a1 = w[0][1], b0 = w[1][0], b1 = w[1][1];
                    { float s0 = tau * (a0 + v1 * b0); a0 -= s0; b0 -= v1 * s0; }
                    { float s0 = tau * (a1 + v1 * b1); a1 -= s0; b1 -= v1 * s0; }
                    { float s0 = tau * (a0 + v1 * a1); a0 -= s0; a1 -= v1 * s0; }
                    { float s0 = tau * (b0 + v1 * b1); b0 -= s0; b1 -= v1 * s0; }
                    if (lane == 0) {
                        H[k * LDH + k - 1] = betac;
                        H[k*LDH+k] = a0; H[k*LDH+k+1] = a1;
                        H[(k+1)*LDH+k] = b0; H[(k+1)*LDH+k+1] = b1;
                    }
                }
                __syncwarp(FULLM);
            }
        }
    }
    __syncwarp(FULLM);

    // ---------------- diagonal block structure ----------------
    int nb;
    {
        int nbl = 0;
        if (lane == 0) {
            int b = 0, i = 0;
            while (i < N) {
                int sz = (i < N - 1 && H[(i + 1) * LDH + i] != 0.f) ? 2 : 1;
                s_cb[b] = i; s_bsz[b] = sz;
                s_bs[i] = i; s_fbi[i] = b;
                if (sz == 2) { s_bs[i + 1] = i; s_fbi[i + 1] = b; }
                i += sz; b++;
            }
            nbl = b;
        }
        __syncwarp(FULLM);
        nb = __shfl_sync(FULLM, nbl, 0);
    }

    // ---------------- amin over eigenvalue magnitudes ----------------
    float amin;
    {
        float em = 3.4e38f;
        #pragma unroll
        for (int rep = 0; rep < 2; rep++) {
            int b = lane + rep * 32;
            if (b < nb) {
                int i = s_cb[b];
                float e;
                if (s_bsz[b] == 1) e = fabsf(H[i * LDH + i]);
                else {
                    float a=H[i*LDH+i], bb=H[i*LDH+i+1], c=H[(i+1)*LDH+i], dd=H[(i+1)*LDH+i+1];
                    float md=0.5f*(a-dd), disc=md*md+bb*c;
                    if (disc < 0.f) e = sqrtf(fmaxf(a*dd - bb*c, 0.f));
                    else { float sq=sqrtf(disc), m2=0.5f*(a+dd); e=fminf(fabsf(m2+sq),fabsf(m2-sq)); }
                }
                em = fminf(em, e);
            }
        }
        #pragma unroll
        for (int off = 16; off >= 1; off >>= 1) em = fminf(em, __shfl_xor_sync(FULLM, em, off));
        amin = em;
    }

    // ---------------- per-block F_II ----------------
    #pragma unroll
    for (int rep = 0; rep < 2; rep++) {
        int b = lane + rep * 32;
        if (b < nb) {
            int i = s_cb[b];
            float e = 1e-6f * amin;
            if (s_bsz[b] == 1) s_f2[b][0] = fabsf(H[i * LDH + i]) + e;
            else {
                float a=H[i*LDH+i], bb=H[i*LDH+i+1], c=H[(i+1)*LDH+i], dd=H[(i+1)*LDH+i+1];
                float md=0.5f*(a-dd), disc=md*md+bb*c, m2=0.5f*(a+dd);
                if (disc < 0.f) {
                    float cc = sqrtf(fmaxf(a*dd - bb*c, 0.f)) + e;
                    s_f2[b][0]=cc; s_f2[b][1]=0.f; s_f2[b][2]=0.f; s_f2[b][3]=cc;
                } else {
                    float sq=sqrtf(disc), l1=m2+sq, l2=m2-sq;
                    float f1=fabsf(l1)+e, f2v=fabsf(l2)+e, al, be;
                    if (fabsf(l1-l2) > 1e-5f*(fabsf(l1)+fabsf(l2)) + 1e-30f) {
                        float idl = 1.f/(l1-l2);
                        al=(f1-f2v)*idl; be=(f2v*l1-f1*l2)*idl;
                    } else { al=(l1>=0.f)?1.f:-1.f; be=f1-al*l1; }
                    s_f2[b][0]=al*a+be; s_f2[b][1]=al*bb; s_f2[b][2]=al*c; s_f2[b][3]=al*dd+be;
                }
            }
        }
    }
    __syncwarp(FULLM);

    // ---------------- block Parlett: F_IJ packed at H[(iJ+c)*LDH + iI+r] ----------------
    for (int pd = 1; pd < nb; pd++) {
        for (int rep = 0; rep < 2; rep++) {
            int I = lane + rep * 32, J = I + pd;
            if (J < nb) {
                int nI=s_bsz[I], nJ=s_bsz[J], iI=s_cb[I], iJ=s_cb[J];
                float TIJ[4], Rv[4]={0,0,0,0};
                for (int r=0;r<nI;r++) for (int c=0;c<nJ;c++) TIJ[r*2+c]=H[(iI+r)*LDH+iJ+c];
                for (int r=0;r<nI;r++) for (int c=0;c<nJ;c++) {
                    float acc=0.f;
                    for (int q=0;q<nI;q++) acc += s_f2[I][r*2+q]*TIJ[q*2+c];
                    for (int q=0;q<nJ;q++) acc -= TIJ[r*2+q]*s_f2[J][q*2+c];
                    Rv[r*2+c]=acc;
                }
                for (int K=I+1;K<J;K++) {
                    int nK=s_bsz[K], iK=s_cb[K];
                    for (int r=0;r<nI;r++) for (int c=0;c<nJ;c++) {
                        float acc=Rv[r*2+c];
                        for (int q=0;q<nK;q++)
                            acc += H[(iK+q)*LDH+iI+r]*H[(iK+q)*LDH+iJ+c]
                                 - H[(iI+r)*LDH+iK+q]*H[(iJ+c)*LDH+iK+q];
                        Rv[r*2+c]=acc;
                    }
                }
                float TII[4], TJJ[4];
                for (int r=0;r<nI;r++) for (int c=0;c<nI;c++) TII[r*2+c]=H[(iI+r)*LDH+iI+c];
                for (int r=0;r<nJ;r++) for (int c=0;c<nJ;c++) TJJ[r*2+c]=H[(iJ+r)*LDH+iJ+c];
                int n = nI * nJ;
                float K4[16], Xv[4];
                for (int c=0;c<nJ;c++) for (int r=0;r<nI;r++) {
                    int row = r + nI*c;
                    for (int c2=0;c2<nJ;c2++) for (int r2=0;r2<nI;r2++) {
                        int col = r2 + nI*c2;
                        float val = 0.f;
                        if (c == c2) val += TII[r*2+r2];
                        if (r == r2) val -= TJJ[c2*2+c];
                        K4[row*4+col] = val;
                    }
                    Xv[row] = Rv[r*2+c];
                }
                for (int p=0;p<n;p++) {
                    int pv=p; float mx=fabsf(K4[p*4+p]);
                    for (int q=p+1;q<n;q++){ float v=fabsf(K4[q*4+p]); if(v>mx){mx=v;pv=q;} }
                    if (pv!=p){ for(int q=p;q<n;q++){float tmp=K4[p*4+q];K4[p*4+q]=K4[pv*4+q];K4[pv*4+q]=tmp;}
                                float tmp=Xv[p];Xv[p]=Xv[pv];Xv[pv]=tmp; }
                    float ip = 1.f / guard(K4[p*4+p]);
                    for (int q=p+1;q<n;q++) {
                        float fc = K4[q*4+p]*ip;
                        for (int q3=p+1;q3<n;q3++) K4[q*4+q3]-=fc*K4[p*4+q3];
                        Xv[q]-=fc*Xv[p];
                    }
                }
                for (int p=n-1;p>=0;p--) {
                    float acc=Xv[p];
                    for (int q=p+1;q<n;q++) acc-=K4[p*4+q]*Xv[q];
                    Xv[p]=acc/guard(K4[p*4+p]);
                }
                for (int c=0;c<nJ;c++) for (int r=0;r<nI;r++) H[(iJ+c)*LDH+iI+r]=Xv[r+nI*c];
            }
        }
        __syncwarp(FULLM);
    }

    // ---------------- G = Q * F -> global scratch (per-lane rows) ----------------
    for (int rep = 0; rep < 2; rep++) {
        int r = lane + rep * 32;
        for (int j = 0; j < N; j++) {
            int bsj = s_bs[j], b = s_fbi[j];
            float a = 0.f;
            for (int i2 = 0; i2 < bsj; i2++) a += Q[r*LDH+i2] * H[j*LDH+i2];
            if (s_bsz[b] == 1) a += Q[r*LDH+j] * s_f2[b][0];
            else {
                int loc = j - bsj;
                a += Q[r*LDH+bsj] * s_f2[b][loc] + Q[r*LDH+bsj+1] * s_f2[b][2+loc];
            }
            Og[r * N + j] = a;
        }
    }
    __syncwarp(FULLM);   // all F reads from H complete before M overwrites H

    // ---------------- M = G * Q^T -> H (lane reads only its OWN G rows) ----------------
    for (int rep = 0; rep < 2; rep++) {
        int r = lane + rep * 32;
        float gr[N];
        #pragma unroll
        for (int kk = 0; kk < N; kk++) gr[kk] = Og[r * N + kk];
        for (int j = 0; j < N; j++) {
            float a = 0.f;
            #pragma unroll
            for (int kk = 0; kk < N; kk++) a += gr[kk] * Q[j * LDH + kk];
            H[r * LDH + j] = a;
        }
    }
    __syncwarp(FULLM);

    for (int idx = lane; idx < N * N; idx += 32) {
        int i = idx >> 6, j = idx & 63;
        Og[idx] = 0.5f * (H[i * LDH + j] + H[j * LDH + i]);
    }
}

extern "C" void kernel_launch(void* const* d_in, const int* in_sizes, int n_in,
                              void* d_out, int out_size) {
    const float* x = (const float*)d_in[0];
    float* out = (float*)d_out;
    int nmat = in_sizes[0] / (N * N);
    size_t smem = 2 * N * LDH * sizeof(float);   // 33,280 B dynamic -> 6 blocks/SM
    spd_project_kernel<<<nmat, 32, smem>>>(x, out, nmat);
}

// round 14
// speedup vs baseline: 1.0008x; 1.0008x over previous
#include <cuda_runtime.h>
#include <math.h>

// One 64x64 matrix per WARP. Francis double-shift QR, fully warp-synchronous:
// rotation + 4x3 bulge window computed redundantly in every lane (registers),
// one __syncwarp per chase step, ballot-based parallel deflation.
// F = f(T) block-Parlett, M = Q F Q^T, out = 0.5(M + M^T).

#define N 64
#define LDH 65
#define ULPF 1.1920929e-7f
#define MAXSW 960
#define FULLM 0xffffffffu

__device__ __forceinline__ float guard(float d){ return (fabsf(d)<1e-25f)?copysignf(1e-25f,d):d; }
__device__ __forceinline__ void gen3(float x,float y,float z,float&tau,float&v1,float&v2,float&beta){
    float ssq=y*y+z*z;
    if(ssq==0.f){tau=0.f;v1=0.f;v2=0.f;beta=x;return;}
    float nrm=sqrtf(x*x+ssq);
    beta=(x>=0.f)?-nrm:nrm;
    tau=(beta-x)/beta; float inv=1.f/(x-beta);
    v1=y*inv; v2=z*inv;
}
__device__ __forceinline__ void gen2(float x,float y,float&tau,float&v1,float&beta){
    if(y==0.f){tau=0.f;v1=0.f;beta=x;return;}
    float nrm=sqrtf(x*x+y*y);
    beta=(x>=0.f)?-nrm:nrm;
    tau=(beta-x)/beta; v1=y/(x-beta);
}

__global__ void __launch_bounds__(32, 6)
spd_project_kernel(const float* __restrict__ X, float* __restrict__ OUT, int nmat)
{
    extern __shared__ float sm[];
    float* H = sm;               // Hessenberg -> T; F packed strictly-lower; later M
    float* Q = sm + N * LDH;

    __shared__ float s_v[N];
    __shared__ int   s_bs[N], s_fbi[N], s_cb[N], s_bsz[N];
    __shared__ float s_f2[N][4];

    const int lane = threadIdx.x;
    const int g = blockIdx.x;
    if (g >= nmat) return;
    const float* A = X + (size_t)g * (N * N);
    float* Og = OUT + (size_t)g * (N * N);

    for (int idx = lane; idx < N * N; idx += 32) {
        int i = idx >> 6, j = idx & 63;
        H[i * LDH + j] = A[idx];
        Q[i * LDH + j] = (i == j) ? 1.f : 0.f;
    }
    __syncwarp(FULLM);

    // ---------------- Hessenberg ----------------
    for (int k = 0; k < N - 2; k++) {
        const int m = N - 1 - k;
        float t = 0.f;
        { int r1 = k + 2 + lane; if (r1 < N) { float h = H[r1 * LDH + k]; t = h * h; } }
        { int r2 = k + 34 + lane; if (r2 < N) { float h = H[r2 * LDH + k]; t += h * h; } }
        #pragma unroll
        for (int off = 16; off >= 1; off >>= 1) t += __shfl_xor_sync(FULLM, t, off);
        const float sigma = t;
        if (sigma > 0.f) {   // uniform
            float x0 = H[(k + 1) * LDH + k];
            float mu = sqrtf(x0 * x0 + sigma);
            float v0 = (x0 <= 0.f) ? (x0 - mu) : (-sigma / (x0 + mu));
            float beta = 2.f * v0 * v0 / (sigma + v0 * v0);
            float iv0 = 1.f / v0;
            #pragma unroll
            for (int rep = 0; rep < 2; rep++) {
                int r = lane + rep * 32;
                if (r < m) s_v[r] = (r == 0) ? 1.f : H[(k + 1 + r) * LDH + k] * iv0;
            }
            __syncwarp(FULLM);
            #pragma unroll
            for (int rep = 0; rep < 2; rep++) {     // left on H cols
                int j = k + lane + rep * 32;
                if (j < N) {
                    float w = 0.f;
                    for (int i = 0; i < m; i++) w += s_v[i] * H[(k + 1 + i) * LDH + j];
                    w *= beta;
                    for (int i = 0; i < m; i++) H[(k + 1 + i) * LDH + j] -= s_v[i] * w;
                }
            }
            #pragma unroll
            for (int rep = 0; rep < 2; rep++) {     // right on Q rows
                int i = lane + rep * 32;
                float wq = 0.f;
                for (int l = 0; l < m; l++) wq += Q[i * LDH + k + 1 + l] * s_v[l];
                wq *= beta;
                for (int l = 0; l < m; l++) Q[i * LDH + k + 1 + l] -= wq * s_v[l];
            }
            __syncwarp(FULLM);
            #pragma unroll
            for (int rep = 0; rep < 2; rep++) {     // right on H rows
                int i = lane + rep * 32;
                float w = 0.f;
                for (int l = 0; l < m; l++) w += H[i * LDH + k + 1 + l] * s_v[l];
                w *= beta;
                for (int l = 0; l < m; l++) H[i * LDH + k + 1 + l] -= w * s_v[l];
                if (i >= k + 2) H[i * LDH + k] = 0.f;
            }
            __syncwarp(FULLM);
        }
    }

    // ---------------- Francis double-shift QR (warp-synchronous) ----------------
    {
        int its = 0, tot = 0, hi = N - 1, prev_hi = -1;
        while (true) {
            // parallel deflation: lane tests subdiags m=lane (bit0=boundary) and m=lane+32
            bool z1 = true, z2;
            if (lane >= 1) {
                int m1 = lane;
                float sub = fabsf(H[m1 * LDH + m1 - 1]);
                float dd = fabsf(H[(m1 - 1) * LDH + m1 - 1]) + fabsf(H[m1 * LDH + m1]);
                z1 = (sub <= ULPF * dd + 1e-30f);
                if (z1) H[m1 * LDH + m1 - 1] = 0.f;
            }
            {
                int m2 = lane + 32;
                float sub = fabsf(H[m2 * LDH + m2 - 1]);
                float dd = fabsf(H[(m2 - 1) * LDH + m2 - 1]) + fabsf(H[m2 * LDH + m2]);
                z2 = (sub <= ULPF * dd + 1e-30f);
                if (z2) H[m2 * LDH + m2 - 1] = 0.f;
            }
            unsigned lowm  = __ballot_sync(FULLM, z1);
            unsigned highm = __ballot_sync(FULLM, z2);
            unsigned long long mask = ((unsigned long long)highm << 32) | (unsigned long long)lowm;
            __syncwarp(FULLM);   // zero-writes visible before any use of H
            // pop converged tail
            while (hi > 0) {
                if ((mask >> hi) & 1ull) hi -= 1;
                else if ((mask >> (hi - 1)) & 1ull) hi -= 2;
                else break;
            }
            if (hi != prev_hi) { its = 0; prev_hi = hi; }
            if (hi <= 0 || tot >= MAXSW) break;
            tot++; its++;
            unsigned long long lm = mask & ((hi >= 63) ? ~0ull : ((1ull << (hi + 1)) - 1ull));
            int lo = 63 - __clzll(lm);

            float t0, d0;
            if (its % 10 == 0) {
                float s2 = fabsf(H[hi * LDH + hi - 1]) + fabsf(H[(hi - 1) * LDH + hi - 2]);
                float h11 = 0.75f * s2 + H[hi * LDH + hi];
                t0 = 2.f * h11; d0 = h11 * h11 + 0.4375f * s2 * s2;
            } else {
                t0 = H[(hi - 1) * LDH + hi - 1] + H[hi * LDH + hi];
                d0 = H[(hi - 1) * LDH + hi - 1] * H[hi * LDH + hi]
                   - H[(hi - 1) * LDH + hi] * H[hi * LDH + hi - 1];
            }
            float h00 = H[lo * LDH + lo],       h01 = H[lo * LDH + lo + 1];
            float h10 = H[(lo + 1) * LDH + lo], h11v = H[(lo + 1) * LDH + lo + 1];
            float h21 = H[(lo + 2) * LDH + lo + 1];
            float tau, v1, v2, betac;
            gen3(h00*h00 + h01*h10 - t0*h00 + d0, h10*(h00 + h11v - t0), h21*h10, tau, v1, v2, betac);

            float w[4][3];                       // window, redundant in every lane
            #pragma unroll
            for (int r = 0; r < 3; r++)
                #pragma unroll
                for (int c = 0; c < 3; c++) w[r][c] = H[(lo + r) * LDH + lo + c];
            { bool r3 = (lo + 3 <= hi);
              #pragma unroll
              for (int c = 0; c < 3; c++) w[3][c] = r3 ? H[(lo + 3) * LDH + lo + c] : 0.f; }
            __syncwarp(FULLM);                   // control reads before chase writes

            for (int k = lo; k < hi; k++) {
                bool last = (k == hi - 1);
                float a1s = 0.f, a2s = 0.f;
                int jb = last ? (k + 2) : (k + 3);
                #pragma unroll
                for (int rep = 0; rep < 2; rep++) {          // left: rows k..k+2
                    int j = jb + lane + rep * 32;
                    if (j < N) {
                        float a0 = H[k * LDH + j], a1 = H[(k + 1) * LDH + j];
                        if (!last) {
                            float a2 = H[(k + 2) * LDH + j];
                            float s0 = tau * (a0 + v1 * a1 + v2 * a2);
                            H[k * LDH + j] = a0 - s0;
                            float n1 = a1 - v1 * s0, n2 = a2 - v2 * s0;
                            H[(k + 1) * LDH + j] = n1; H[(k + 2) * LDH + j] = n2;
                            if (rep == 0 && lane == 0) { a1s = n1; a2s = n2; }
                        } else {
                            float s0 = tau * (a0 + v1 * a1);
                            H[k * LDH + j] = a0 - s0; H[(k + 1) * LDH + j] = a1 - v1 * s0;
                        }
                    }
                }
                #pragma unroll
                for (int rep = 0; rep < 2; rep++) {          // right: rows < k
                    int i = lane + rep * 32;
                    if (i < k) {
                        float a0 = H[i * LDH + k], a1 = H[i * LDH + k + 1];
                        if (!last) {
                            float a2 = H[i * LDH + k + 2];
                            float s0 = tau * (a0 + v1 * a1 + v2 * a2);
                            H[i*LDH+k] = a0 - s0; H[i*LDH+k+1] = a1 - v1*s0; H[i*LDH+k+2] = a2 - v2*s0;
                        } else {
                            float s0 = tau * (a0 + v1 * a1);
                            H[i*LDH+k] = a0 - s0; H[i*LDH+k+1] = a1 - v1*s0;
                        }
                    }
                }
                #pragma unroll
                for (int rep = 0; rep < 2; rep++) {          // Q right: all rows
                    int i = lane + rep * 32;
                    float q0 = Q[i * LDH + k], q1 = Q[i * LDH + k + 1];
                    if (!last) {
                        float q2 = Q[i * LDH + k + 2];
                        float s0 = tau * (q0 + v1 * q1 + v2 * q2);
                        Q[i*LDH+k] = q0 - s0; Q[i*LDH+k+1] = q1 - v1*s0; Q[i*LDH+k+2] = q2 - v2*s0;
                    } else {
                        float s0 = tau * (q0 + v1 * q1);
                        Q[i*LDH+k] = q0 - s0; Q[i*LDH+k+1] = q1 - v1*s0;
                    }
                }
                if (!last) {
                    #pragma unroll
                    for (int c = 0; c < 3; c++) {            // window col applies
                        float s0 = tau * (w[0][c] + v1 * w[1][c] + v2 * w[2][c]);
                        w[0][c] -= s0; w[1][c] -= v1 * s0; w[2][c] -= v2 * s0;
                    }
                    #pragma unroll
                    for (int r = 0; r < 4; r++) {            // window row applies
                        float s0 = tau * (w[r][0] + v1 * w[r][1] + v2 * w[r][2]);
                        w[r][0] -= s0; w[r][1] -= v1 * s0; w[r][2] -= v2 * s0;
                    }
                    if (lane == 0) {                         // row k exits window
                        if (k > lo) H[k * LDH + k - 1] = betac;
                        H[k*LDH+k] = w[0][0]; H[k*LDH+k+1] = w[0][1]; H[k*LDH+k+2] = w[0][2];
                    }
                    float tn, v1n, v2n = 0.f, bn;
                    if (k + 1 == hi - 1) gen2(w[1][0], w[2][0], tn, v1n, bn);
                    else                 gen3(w[1][0], w[2][0], w[3][0], tn, v1n, v2n, bn);
                    #pragma unroll
                    for (int r = 0; r < 3; r++) { w[r][0] = w[r+1][1]; w[r][1] = w[r+1][2]; }
                    w[3][0] = 0.f; w[3][1] = 0.f;
                    // fresh col k+3: rows k+1,k+2 via shfl from lane0; k+3,k+4 race-free smem
                    w[0][2] = __shfl_sync(FULLM, a1s, 0);
                    w[1][2] = __shfl_sync(FULLM, a2s, 0);
                    w[2][2] = (k + 3 <= hi) ? H[(k + 3) * LDH + (k + 3)] : 0.f;
                    w[3][2] = (k + 4 <= hi) ? H[(k + 4) * LDH + (k + 3)] : 0.f;
                    tau = tn; v1 = v1n; v2 = v2n; betac = bn;
                } else {
                    float a0 = w[0][0], a1 = w[0][1], b0 = w[1][0], b1 = w[1][1];
                    { float s0 = tau * (a0 + v1 * b0); a0 -= s0; b0 -= v1 * s0; }
                    { float s0 = tau * (a1 + v1 * b1); a1 -= s0; b1 -= v1 * s0; }
                    { float s0 = tau * (a0 + v1 * a1); a0 -= s0; a1 -= v1 * s0; }
                    { float s0 = tau * (b0 + v1 * b1); b0 -= s0; b1 -= v1 * s0; }
                    if (lane == 0) {
                        H[k * LDH + k - 1] = betac;
                        H[k*LDH+k] = a0; H[k*LDH+k+1] = a1;
                        H[(k+1)*LDH+k] = b0; H[(k+1)*LDH+k+1] = b1;
                    }
                }
                __syncwarp(FULLM);
            }
        }
    }
    __syncwarp(FULLM);

    // ---------------- diagonal block structure ----------------
    int nb;
    {
        int nbl = 0;
        if (lane == 0) {
            int b = 0, i = 0;
            while (i < N) {
                int sz = (i < N - 1 && H[(i + 1) * LDH + i] != 0.f) ? 2 : 1;
                s_cb[b] = i; s_bsz[b] = sz;
                s_bs[i] = i; s_fbi[i] = b;
                if (sz == 2) { s_bs[i + 1] = i; s_fbi[i + 1] = b; }
                i += sz; b++;
            }
            nbl = b;
        }
        __syncwarp(FULLM);
        nb = __shfl_sync(FULLM, nbl, 0);
    }

    // ---------------- amin over eigenvalue magnitudes ----------------
    float amin;
    {
        float em = 3.4e38f;
        #pragma unroll
        for (int rep = 0; rep < 2; rep++) {
            int b = lane + rep * 32;
            if (b < nb) {
                int i = s_cb[b];
                float e;
                if (s_bsz[b] == 1) e = fabsf(H[i * LDH + i]);
                else {
                    float a=H[i*LDH+i], bb=H[i*LDH+i+1], c=H[(i+1)*LDH+i], dd=H[(i+1)*LDH+i+1];
                    float md=0.5f*(a-dd), disc=md*md+bb*c;
                    if (disc < 0.f) e = sqrtf(fmaxf(a*dd - bb*c, 0.f));
                    else { float sq=sqrtf(disc), m2=0.5f*(a+dd); e=fminf(fabsf(m2+sq),fabsf(m2-sq)); }
                }
                em = fminf(em, e);
            }
        }
        #pragma unroll
        for (int off = 16; off >= 1; off >>= 1) em = fminf(em, __shfl_xor_sync(FULLM, em, off));
        amin = em;
    }

    // ---------------- per-block F_II ----------------
    #pragma unroll
    for (int rep = 0; rep < 2; rep++) {
        int b = lane + rep * 32;
        if (b < nb) {
            int i = s_cb[b];
            float e = 1e-6f * amin;
            if (s_bsz[b] == 1) s_f2[b][0] = fabsf(H[i * LDH + i]) + e;
            else {
                float a=H[i*LDH+i], bb=H[i*LDH+i+1], c=H[(i+1)*LDH+i], dd=H[(i+1)*LDH+i+1];
                float md=0.5f*(a-dd), disc=md*md+bb*c, m2=0.5f*(a+dd);
                if (disc < 0.f) {
                    float cc = sqrtf(fmaxf(a*dd - bb*c, 0.f)) + e;
                    s_f2[b][0]=cc; s_f2[b][1]=0.f; s_f2[b][2]=0.f; s_f2[b][3]=cc;
                } else {
                    float sq=sqrtf(disc), l1=m2+sq, l2=m2-sq;
                    float f1=fabsf(l1)+e, f2v=fabsf(l2)+e, al, be;
                    if (fabsf(l1-l2) > 1e-5f*(fabsf(l1)+fabsf(l2)) + 1e-30f) {
                        float idl = 1.f/(l1-l2);
                        al=(f1-f2v)*idl; be=(f2v*l1-f1*l2)*idl;
                    } else { al=(l1>=0.f)?1.f:-1.f; be=f1-al*l1; }
                    s_f2[b][0]=al*a+be; s_f2[b][1]=al*bb; s_f2[b][2]=al*c; s_f2[b][3]=al*dd+be;
                }
            }
        }
    }
    __syncwarp(FULLM);

    // ---------------- block Parlett: F_IJ packed at H[(iJ+c)*LDH + iI+r] ----------------
    for (int pd = 1; pd < nb; pd++) {
        for (int rep = 0; rep < 2; rep++) {
            int I = lane + rep * 32, J = I + pd;
            if (J < nb) {
                int nI=s_bsz[I], nJ=s_bsz[J], iI=s_cb[I], iJ=s_cb[J];
                float TIJ[4], Rv[4]={0,0,0,0};
                for (int r=0;r<nI;r++) for (int c=0;c<nJ;c++) TIJ[r*2+c]=H[(iI+r)*LDH+iJ+c];
                for (int r=0;r<nI;r++) for (int c=0;c<nJ;c++) {
                    float acc=0.f;
                    for (int q=0;q<nI;q++) acc += s_f2[I][r*2+q]*TIJ[q*2+c];
                    for (int q=0;q<nJ;q++) acc -= TIJ[r*2+q]*s_f2[J][q*2+c];
                    Rv[r*2+c]=acc;
                }
                for (int K=I+1;K<J;K++) {
                    int nK=s_bsz[K], iK=s_cb[K];
                    for (int r=0;r<nI;r++) for (int c=0;c<nJ;c++) {
                        float acc=Rv[r*2+c];
                        for (int q=0;q<nK;q++)
                            acc += H[(iK+q)*LDH+iI+r]*H[(iK+q)*LDH+iJ+c]
                                 - H[(iI+r)*LDH+iK+q]*H[(iJ+c)*LDH+iK+q];
                        Rv[r*2+c]=acc;
                    }
                }
                float TII[4], TJJ[4];
                for (int r=0;r<nI;r++) for (int c=0;c<nI;c++) TII[r*2+c]=H[(iI+r)*LDH+iI+c];
                for (int r=0;r<nJ;r++) for (int c=0;c<nJ;c++) TJJ[r*2+c]=H[(iJ+r)*LDH+iJ+c];
                int n = nI * nJ;
                float K4[16], Xv[4];
                for (int c=0;c<nJ;c++) for (int r=0;r<nI;r++) {
                    int row = r + nI*c;
                    for (int c2=0;c2<nJ;c2++) for (int r2=0;r2<nI;r2++) {
                        int col = r2 + nI*c2;
                        float val = 0.f;
                        if (c == c2) val += TII[r*2+r2];
                        if (r == r2) val -= TJJ[c2*2+c];
                        K4[row*4+col] = val;
                    }
                    Xv[row] = Rv[r*2+c];
                }
                for (int p=0;p<n;p++) {
                    int pv=p; float mx=fabsf(K4[p*4+p]);
                    for (int q=p+1;q<n;q++){ float v=fabsf(K4[q*4+p]); if(v>mx){mx=v;pv=q;} }
                    if (pv!=p){ for(int q=p;q<n;q++){float tmp=K4[p*4+q];K4[p*4+q]=K4[pv*4+q];K4[pv*4+q]=tmp;}
                                float tmp=Xv[p];Xv[p]=Xv[pv];Xv[pv]=tmp; }
                    float ip = 1.f / guard(K4[p*4+p]);
                    for (int q=p+1;q<n;q++) {
                        float fc = K4[q*4+p]*ip;
                        for (int q3=p+1;q3<n;q3++) K4[q*4+q3]-=fc*K4[p*4+q3];
                        Xv[q]-=fc*Xv[p];
                    }
                }
                for (int p=n-1;p>=0;p--) {
                    float acc=Xv[p];
                    for (int q=p+1;q<n;q++) acc-=K4[p*4+q]*Xv[q];
                    Xv[p]=acc/guard(K4[p*4+p]);
                }
                for (int c=0;c<nJ;c++) for (int r=0;r<nI;r++) H[(iJ+c)*LDH+iI+r]=Xv[r+nI*c];
            }
        }
        __syncwarp(FULLM);
    }

    // ---------------- G = Q * F -> global scratch (per-lane rows) ----------------
    for (int rep = 0; rep < 2; rep++) {
        int r = lane + rep * 32;
        for (int j = 0; j < N; j++) {
            int bsj = s_bs[j], b = s_fbi[j];
            float a = 0.f;
            for (int i2 = 0; i2 < bsj; i2++) a += Q[r*LDH+i2] * H[j*LDH+i2];
            if (s_bsz[b] == 1) a += Q[r*LDH+j] * s_f2[b][0];
            else {
                int loc = j - bsj;
                a += Q[r*LDH+bsj] * s_f2[b][loc] + Q[r*LDH+bsj+1] * s_f2[b][2+loc];
            }
            Og[r * N + j] = a;
        }
    }
    __syncwarp(FULLM);   // all F reads from H complete before M overwrites H

    // ---------------- M = G * Q^T -> H (lane reads only its OWN G rows) ----------------
    for (int rep = 0; rep < 2; rep++) {
        int r = lane + rep * 32;
        float gr[N];
        #pragma unroll
        for (int kk = 0; kk < N; kk++) gr[kk] = Og[r * N + kk];
        for (int j = 0; j < N; j++) {
            float a = 0.f;
            #pragma unroll
            for (int kk = 0; kk < N; kk++) a += gr[kk] * Q[j * LDH + kk];
            H[r * LDH + j] = a;
        }
    }
    __syncwarp(FULLM);

    for (int idx = lane; idx < N * N; idx += 32) {
        int i = idx >> 6, j = idx & 63;
        Og[idx] = 0.5f * (H[i * LDH + j] + H[j * LDH + i]);
    }
}

extern "C" void kernel_launch(void* const* d_in, const int* in_sizes, int n_in,
                              void* d_out, int out_size) {
    const float* x = (const float*)d_in[0];
    float* out = (float*)d_out;
    int nmat = in_sizes[0] / (N * N);
    size_t smem = 2 * N * LDH * sizeof(float);   // 33,280 B dynamic -> 6 blocks/SM
    spd_project_kernel<<<nmat, 32, smem>>>(x, out, nmat);
}

// round 15
// speedup vs baseline: 1.3274x; 1.3264x over previous
#include <cuda_runtime.h>
#include <math.h>

#define N 64
#define LDH 65
#define ULPF 1.1920929e-7f
#define MAXSW 960
#define NT 128
#define FULLM 0xffffffffu

__device__ __forceinline__ float guard(float d){ return (fabsf(d)<1e-25f)?copysignf(1e-25f,d):d; }
__device__ __forceinline__ void gen3(float x,float y,float z,float&tau,float&v1,float&v2,float&beta){
    float ssq=y*y+z*z;
    if(ssq==0.f){tau=0.f;v1=0.f;v2=0.f;beta=x;return;}
    float nrm=sqrtf(x*x+ssq);
    beta=(x>=0.f)?-nrm:nrm;
    tau=(beta-x)/beta; float inv=1.f/(x-beta);
    v1=y*inv; v2=z*inv;
}
__device__ __forceinline__ void gen2(float x,float y,float&tau,float&v1,float&beta){
    if(y==0.f){tau=0.f;v1=0.f;beta=x;return;}
    float nrm=sqrtf(x*x+y*y);
    beta=(x>=0.f)?-nrm:nrm;
    tau=(beta-x)/beta; v1=y/(x-beta);
}

__global__ void __launch_bounds__(NT, 6)
spd_project_kernel(const float* __restrict__ X, float* __restrict__ OUT, int nmat)
{
    extern __shared__ float sm[];
    float* H = sm;
    float* Q = sm + N * LDH;

    __shared__ float  s_red[4];
    __shared__ float  s_v[N];
    __shared__ int    s_bs[N], s_fbi[N], s_cb[N], s_bsz[N];
    __shared__ float  s_f2[N][4];
    __shared__ int    s_nb;
    __shared__ float  s_amin;
    __shared__ float4 s_mb[2];

    const int tid = threadIdx.x, warp = tid >> 5, lane = tid & 31;
    const int g = blockIdx.x;
    if (g >= nmat) return;
    const float* A = X + (size_t)g * (N * N);
    float* Og = OUT + (size_t)g * (N * N);

    for (int idx = tid; idx < N * N; idx += NT) {
        int i = idx >> 6, j = idx & 63;
        H[i * LDH + j] = A[idx];
        Q[i * LDH + j] = (i == j) ? 1.f : 0.f;
    }
    __syncthreads();

    // ---------- Hessenberg ----------
    for (int k = 0; k < N - 2; k++) {
        const int m = N - 1 - k;
        float t = 0.f;
        { int row = k + 2 + tid; if (row < N) { float h = H[row * LDH + k]; t = h * h; } }
        #pragma unroll
        for (int off = 16; off >= 1; off >>= 1) t += __shfl_xor_sync(FULLM, t, off);
        if (lane == 0) s_red[warp] = t;
        __syncthreads();
        const float sigma = s_red[0] + s_red[1] + s_red[2] + s_red[3];
        if (sigma > 0.f) {
            float x0 = H[(k + 1) * LDH + k];
            float mu = sqrtf(x0 * x0 + sigma);
            float v0 = (x0 <= 0.f) ? (x0 - mu) : (-sigma / (x0 + mu));
            float beta = 2.f * v0 * v0 / (sigma + v0 * v0);
            float iv0 = 1.f / v0;
            if (tid < m) s_v[tid] = (tid == 0) ? 1.f : H[(k + 1 + tid) * LDH + k] * iv0;
            __syncthreads();
            if (tid < 64) {
                int j = k + tid;
                if (j < N) {
                    float w = 0.f;
                    for (int i = 0; i < m; i++) w += s_v[i] * H[(k + 1 + i) * LDH + j];
                    w *= beta;
                    for (int i = 0; i < m; i++) H[(k + 1 + i) * LDH + j] -= s_v[i] * w;
                }
            } else {
                int i = tid - 64;
                float wq = 0.f;
                for (int l = 0; l < m; l++) wq += Q[i * LDH + k + 1 + l] * s_v[l];
                wq *= beta;
                for (int l = 0; l < m; l++) Q[i * LDH + k + 1 + l] -= wq * s_v[l];
            }
            __syncthreads();
            if (tid < N) {
              int i = tid;
              float w = 0.f;
              for (int l = 0; l < m; l++) w += H[i * LDH + k + 1 + l] * s_v[l];
              w *= beta;
              for (int l = 0; l < m; l++) H[i * LDH + k + 1 + l] -= w * s_v[l];
              if (i >= k + 2) H[i * LDH + k] = 0.f;
            }
            __syncthreads();
        } else __syncthreads();
    }

    // ---------- Francis double-shift QR (ballot deflation + banded applies) ----------
    {
        int its = 0, tot = 0, hi = N - 1, prev_hi = -1;
        float w[4][3];       // owner window (warp3 lane0)
        float cc[2][2];      // per-warp role carries
        float tau, v1, v2, betac;
        while (true) {
            bool z1 = true, z2;
            if (lane >= 1) {
                int m1 = lane;
                float sub = fabsf(H[m1 * LDH + m1 - 1]);
                float dd = fabsf(H[(m1 - 1) * LDH + m1 - 1]) + fabsf(H[m1 * LDH + m1]);
                z1 = (sub <= ULPF * dd + 1e-30f);
                if (z1) H[m1 * LDH + m1 - 1] = 0.f;
            }
            {
                int m2 = lane + 32;
                float sub = fabsf(H[m2 * LDH + m2 - 1]);
                float dd = fabsf(H[(m2 - 1) * LDH + m2 - 1]) + fabsf(H[m2 * LDH + m2]);
                z2 = (sub <= ULPF * dd + 1e-30f);
                if (z2) H[m2 * LDH + m2 - 1] = 0.f;
            }
            unsigned lowm = __ballot_sync(FULLM, z1), highm = __ballot_sync(FULLM, z2);
            unsigned long long mask = ((unsigned long long)highm << 32) | (unsigned long long)lowm;
            __syncwarp(FULLM);
            while (hi > 0) {
                if ((mask >> hi) & 1ull) hi -= 1;
                else if ((mask >> (hi - 1)) & 1ull) hi -= 2;
                else break;
            }
            if (hi != prev_hi) { its = 0; prev_hi = hi; }
            if (hi <= 0 || tot >= MAXSW) break;
            tot++; its++;
            unsigned long long lm = mask & ((hi >= 63) ? ~0ull : ((1ull << (hi + 1)) - 1ull));
            int lo = 63 - __clzll(lm);

            float t0, d0;
            if (its % 10 == 0) {
                float s2 = fabsf(H[hi * LDH + hi - 1]) + fabsf(H[(hi - 1) * LDH + hi - 2]);
                float h11 = 0.75f * s2 + H[hi * LDH + hi];
                t0 = 2.f * h11; d0 = h11 * h11 + 0.4375f * s2 * s2;
            } else {
                t0 = H[(hi - 1) * LDH + hi - 1] + H[hi * LDH + hi];
                d0 = H[(hi - 1) * LDH + hi - 1] * H[hi * LDH + hi]
                   - H[(hi - 1) * LDH + hi] * H[hi * LDH + hi - 1];
            }
            float h00 = H[lo * LDH + lo],       h01 = H[lo * LDH + lo + 1];
            float h10 = H[(lo + 1) * LDH + lo], h11v = H[(lo + 1) * LDH + lo + 1];
            float h21 = H[(lo + 2) * LDH + lo + 1];
            gen3(h00*h00 + h01*h10 - t0*h00 + d0, h10*(h00 + h11v - t0), h21*h10, tau, v1, v2, betac);

            if (tid == 96) {
                #pragma unroll
                for (int r = 0; r < 3; r++)
                    #pragma unroll
                    for (int c = 0; c < 3; c++) w[r][c] = H[(lo + r) * LDH + lo + c];
                bool r3 = (lo + 3 <= hi);
                #pragma unroll
                for (int c = 0; c < 3; c++) w[3][c] = r3 ? H[(lo + 3) * LDH + lo + c] : 0.f;
            }
            __syncthreads();   // control reads before chase writes

            for (int k = lo; k < hi; k++) {
                bool last = (k == hi - 1);
                if (k > lo && tid < 96) { float4 mb = s_mb[k & 1]; tau = mb.x; v1 = mb.y; v2 = mb.z; }
                if (warp == 0) {                       // left: fixed column j
                    #pragma unroll
                    for (int rep = 0; rep < 2; rep++) {
                        int j = lane + rep * 32;
                        if (!last) {
                            if (j >= k + 3) {
                                float c0, c1;
                                if (k == lo) { c0 = H[k*LDH+j]; c1 = H[(k+1)*LDH+j]; }
                                else         { c0 = cc[rep][0]; c1 = cc[rep][1]; }
                                float c2 = H[(k + 2) * LDH + j];
                                float s0 = tau * (c0 + v1 * c1 + v2 * c2);
                                float n1 = c1 - v1 * s0, n2 = c2 - v2 * s0;
                                H[k * LDH + j] = c0 - s0;
                                if (j == k + 3) { H[(k+1)*LDH+j] = n1; H[(k+2)*LDH+j] = n2; }
                                cc[rep][0] = n1; cc[rep][1] = n2;
                            }
                        } else {
                            if (j >= k + 2) {
                                float c0, c1;
                                if (k == lo) { c0 = H[k*LDH+j]; c1 = H[(k+1)*LDH+j]; }
                                else         { c0 = cc[rep][0]; c1 = cc[rep][1]; }
                                float s0 = tau * (c0 + v1 * c1);
                                H[k * LDH + j] = c0 - s0; H[(k + 1) * LDH + j] = c1 - v1 * s0;
                            }
                        }
                    }
                } else if (warp == 1) {                // right: fixed row i
                    #pragma unroll
                    for (int rep = 0; rep < 2; rep++) {
                        int i = lane + rep * 32;
                        if (i < k) {
                            float c0, c1;
                            if (k == lo || i == k - 1) { c0 = H[i*LDH+k]; c1 = H[i*LDH+k+1]; }
                            else                       { c0 = cc[rep][0]; c1 = cc[rep][1]; }
                            if (!last) {
                                float c2 = H[i * LDH + k + 2];
                                float s0 = tau * (c0 + v1 * c1 + v2 * c2);
                                H[i * LDH + k] = c0 - s0;
                                cc[rep][0] = c1 - v1 * s0; cc[rep][1] = c2 - v2 * s0;
                            } else {
                                float s0 = tau * (c0 + v1 * c1);
                                H[i*LDH+k] = c0 - s0; H[i*LDH+k+1] = c1 - v1 * s0;
                            }
                        }
                    }
                } else if (warp == 2) {                // Q: fixed row i
                    #pragma unroll
                    for (int rep = 0; rep < 2; rep++) {
                        int i = lane + rep * 32;
                        float c0, c1;
                        if (k == lo) { c0 = Q[i*LDH+k]; c1 = Q[i*LDH+k+1]; }
                        else         { c0 = cc[rep][0]; c1 = cc[rep][1]; }
                        if (!last) {
                            float c2 = Q[i * LDH + k + 2];
                            float s0 = tau * (c0 + v1 * c1 + v2 * c2);
                            Q[i * LDH + k] = c0 - s0;
                            cc[rep][0] = c1 - v1 * s0; cc[rep][1] = c2 - v2 * s0;
                        } else {
                            float s0 = tau * (c0 + v1 * c1);
                            Q[i*LDH+k] = c0 - s0; Q[i*LDH+k+1] = c1 - v1 * s0;
                        }
                    }
                } else if (lane == 0) {                // owner (tid 96)
                    if (!last) {
                        if (k > lo) H[k * LDH + k - 1] = betac;
                        #pragma unroll
                        for (int c = 0; c < 3; c++) {
                            float s0 = tau * (w[0][c] + v1 * w[1][c] + v2 * w[2][c]);
                            w[0][c] -= s0; w[1][c] -= v1 * s0; w[2][c] -= v2 * s0;
                        }
                        #pragma unroll
                        for (int r = 0; r < 4; r++) {
                            float s0 = tau * (w[r][0] + v1 * w[r][1] + v2 * w[r][2]);
                            w[r][0] -= s0; w[r][1] -= v1 * s0; w[r][2] -= v2 * s0;
                        }
                        float tn, v1n, v2n = 0.f, bn;
                        if (k + 1 == hi - 1) { gen2(w[1][0], w[2][0], tn, v1n, bn); }
                        else                 { gen3(w[1][0], w[2][0], w[3][0], tn, v1n, v2n, bn); }
                        s_mb[(k + 1) & 1] = make_float4(tn, v1n, v2n, 0.f);
                        H[k*LDH+k] = w[0][0]; H[k*LDH+k+1] = w[0][1]; H[k*LDH+k+2] = w[0][2];
                        #pragma unroll
                        for (int r = 0; r < 3; r++) { w[r][0] = w[r+1][1]; w[r][1] = w[r+1][2]; }
                        w[3][0] = 0.f; w[3][1] = 0.f;
                        tau = tn; v1 = v1n; v2 = v2n; betac = bn;
                    } else {
                        H[k * LDH + k - 1] = betac;
                        float a0 = w[0][0], a1 = w[0][1], b0 = w[1][0], b1 = w[1][1];
                        { float s0 = tau * (a0 + v1 * b0); a0 -= s0; b0 -= v1 * s0; }
                        { float s0 = tau * (a1 + v1 * b1); a1 -= s0; b1 -= v1 * s0; }
                        { float s0 = tau * (a0 + v1 * a1); a0 -= s0; a1 -= v1 * s0; }
                        { float s0 = tau * (b0 + v1 * b1); b0 -= s0; b1 -= v1 * s0; }
                        H[k*LDH+k] = a0; H[k*LDH+k+1] = a1;
                        H[(k+1)*LDH+k] = b0; H[(k+1)*LDH+k+1] = b1;
                    }
                }
                __syncthreads();
                if (tid == 96 && k + 1 < hi) {         // fresh col k+3 for next window
                    int c3 = k + 3;
                    w[0][2] = H[(k + 1) * LDH + c3];
                    w[1][2] = (k + 2 <= hi) ? H[(k + 2) * LDH + c3] : 0.f;
                    w[2][2] = (k + 3 <= hi) ? H[(k + 3) * LDH + c3] : 0.f;
                    w[3][2] = (k + 4 <= hi) ? H[(k + 4) * LDH + c3] : 0.f;
                }
            }
        }
    }
    __syncthreads();

    // ---------- diagonal blocks ----------
    if (tid == 0) {
        int b = 0, i = 0;
        while (i < N) {
            int sz = (i < N - 1 && H[(i + 1) * LDH + i] != 0.f) ? 2 : 1;
            s_cb[b] = i; s_bsz[b] = sz;
            s_bs[i] = i; s_fbi[i] = b;
            if (sz == 2) { s_bs[i + 1] = i; s_fbi[i + 1] = b; }
            i += sz; b++;
        }
        s_nb = b;
    }
    __syncthreads();
    const int nb = s_nb;

    // ---------- amin ----------
    {
        float em = 3.4e38f;
        if (tid < nb) {
            int i = s_cb[tid];
            if (s_bsz[tid] == 1) em = fabsf(H[i * LDH + i]);
            else {
                float a=H[i*LDH+i], b=H[i*LDH+i+1], c=H[(i+1)*LDH+i], dd=H[(i+1)*LDH+i+1];
                float md=0.5f*(a-dd), disc=md*md+b*c;
                if (disc < 0.f) em = sqrtf(fmaxf(a*dd - b*c, 0.f));
                else { float sq=sqrtf(disc), m2=0.5f*(a+dd); em=fminf(fabsf(m2+sq),fabsf(m2-sq)); }
            }
        }
        #pragma unroll
        for (int off = 16; off >= 1; off >>= 1) em = fminf(em, __shfl_xor_sync(FULLM, em, off));
        if (lane == 0) s_red[warp] = em;
        __syncthreads();
        if (tid == 0) s_amin = fminf(fminf(s_red[0], s_red[1]), fminf(s_red[2], s_red[3]));
        __syncthreads();
    }

    // ---------- per-block F_II ----------
    if (tid < nb) {
        int i = s_cb[tid];
        float e = 1e-6f * s_amin;
        if (s_bsz[tid] == 1) s_f2[tid][0] = fabsf(H[i * LDH + i]) + e;
        else {
            float a=H[i*LDH+i], b=H[i*LDH+i+1], c=H[(i+1)*LDH+i], dd=H[(i+1)*LDH+i+1];
            float md=0.5f*(a-dd), disc=md*md+b*c, m2=0.5f*(a+dd);
            if (disc < 0.f) {
                float ccn = sqrtf(fmaxf(a*dd - b*c, 0.f)) + e;
                s_f2[tid][0]=ccn; s_f2[tid][1]=0.f; s_f2[tid][2]=0.f; s_f2[tid][3]=ccn;
            } else {
                float sq=sqrtf(disc), l1=m2+sq, l2=m2-sq;
                float f1=fabsf(l1)+e, f2=fabsf(l2)+e, al, be;
                if (fabsf(l1-l2) > 1e-5f*(fabsf(l1)+fabsf(l2)) + 1e-30f) {
                    float idl = 1.f/(l1-l2);
                    al=(f1-f2)*idl; be=(f2*l1-f1*l2)*idl;
                } else { al=(l1>=0.f)?1.f:-1.f; be=f1-al*l1; }
                s_f2[tid][0]=al*a+be; s_f2[tid][1]=al*b; s_f2[tid][2]=al*c; s_f2[tid][3]=al*dd+be;
            }
        }
    }
    __syncthreads();

    // ---------- block Parlett: F_IJ packed at H[(iJ+c)*LDH + iI+r] ----------
    for (int pd = 1; pd < nb; pd++) {
        int I = tid, J = I + pd;
        if (J < nb) {
            int nI=s_bsz[I], nJ=s_bsz[J], iI=s_cb[I], iJ=s_cb[J];
            float TIJ[4], Rv[4]={0,0,0,0};
            for (int r=0;r<nI;r++) for (int c=0;c<nJ;c++) TIJ[r*2+c]=H[(iI+r)*LDH+iJ+c];
            for (int r=0;r<nI;r++) for (int c=0;c<nJ;c++) {
                float acc=0.f;
                for (int q=0;q<nI;q++) acc += s_f2[I][r*2+q]*TIJ[q*2+c];
                for (int q=0;q<nJ;q++) acc -= TIJ[r*2+q]*s_f2[J][q*2+c];
                Rv[r*2+c]=acc;
            }
            for (int K=I+1;K<J;K++) {
                int nK=s_bsz[K], iK=s_cb[K];
                for (int r=0;r<nI;r++) for (int c=0;c<nJ;c++) {
                    float acc=Rv[r*2+c];
                    for (int q=0;q<nK;q++)
                        acc += H[(iK+q)*LDH+iI+r]*H[(iK+q)*LDH+iJ+c]
                             - H[(iI+r)*LDH+iK+q]*H[(iJ+c)*LDH+iK+q];
                    Rv[r*2+c]=acc;
                }
            }
            float TII[4], TJJ[4];
            for (int r=0;r<nI;r++) for (int c=0;c<nI;c++) TII[r*2+c]=H[(iI+r)*LDH+iI+c];
            for (int r=0;r<nJ;r++) for (int c=0;c<nJ;c++) TJJ[r*2+c]=H[(iJ+r)*LDH+iJ+c];
            int n = nI * nJ;
            float K4[16], Xv[4];
            for (int c=0;c<nJ;c++) for (int r=0;r<nI;r++) {
                int row = r + nI*c;
                for (int c2=0;c2<nJ;c2++) for (int r2=0;r2<nI;r2++) {
                    int col = r2 + nI*c2;
                    float val = 0.f;
                    if (c == c2) val += TII[r*2+r2];
                    if (r == r2) val -= TJJ[c2*2+c];
                    K4[row*4+col] = val;
                }
                Xv[row] = Rv[r*2+c];
            }
            for (int p=0;p<n;p++) {
                int pv=p; float mx=fabsf(K4[p*4+p]);
                for (int q=p+1;q<n;q++){ float v=fabsf(K4[q*4+p]); if(v>mx){mx=v;pv=q;} }
                if (pv!=p){ for(int q=p;q<n;q++){float tmp=K4[p*4+q];K4[p*4+q]=K4[pv*4+q];K4[pv*4+q]=tmp;}
                            float tmp=Xv[p];Xv[p]=Xv[pv];Xv[pv]=tmp; }
                float ip = 1.f / guard(K4[p*4+p]);
                for (int q=p+1;q<n;q++) {
                    float fc = K4[q*4+p]*ip;
                    for (int q3=p+1;q3<n;q3++) K4[q*4+q3]-=fc*K4[p*4+q3];
                    Xv[q]-=fc*Xv[p];
                }
            }
            for (int p=n-1;p>=0;p--) {
                float acc=Xv[p];
                for (int q=p+1;q<n;q++) acc-=K4[p*4+q]*Xv[q];
                Xv[p]=acc/guard(K4[p*4+p]);
            }
            for (int c=0;c<nJ;c++) for (int r=0;r<nI;r++) H[(iJ+c)*LDH+iI+r]=Xv[r+nI*c];
        }
        __syncthreads();
    }

    // ---------- G = Q * F (2 threads per row) ----------
    {
        const int r = tid & 63, half = tid >> 6;
        float acc[32];
        for (int jj = 0; jj < 32; jj++) {
            int j = half * 32 + jj;
            int bsj = s_bs[j], b = s_fbi[j];
            float a = 0.f;
            for (int i2 = 0; i2 < bsj; i2++) a += Q[r*LDH+i2] * H[j*LDH+i2];
            if (s_bsz[b] == 1) a += Q[r*LDH+j] * s_f2[b][0];
            else {
                int loc = j - bsj;
                a += Q[r*LDH+bsj] * s_f2[b][loc] + Q[r*LDH+bsj+1] * s_f2[b][2+loc];
            }
            acc[jj] = a;
        }
        __syncthreads();
        for (int jj = 0; jj < 32; jj++) H[r*LDH + half*32 + jj] = acc[jj];
    }
    __syncthreads();

    // ---------- M = G * Q^T (2 threads per row) ----------
    {
        const int r = tid & 63, half = tid >> 6;
        float acc[32];
        for (int jj = 0; jj < 32; jj++) {
            int j = half * 32 + jj;
            float a = 0.f;
            for (int kk = 0; kk < N; kk++) a += H[r*LDH+kk] * Q[j*LDH+kk];
            acc[jj] = a;
        }
        __syncthreads();
        for (int jj = 0; jj < 32; jj++) H[r*LDH + half*32 + jj] = acc[jj];
    }
    __syncthreads();

    for (int idx = tid; idx < N * N; idx += NT) {
        int i = idx >> 6, j = idx & 63;
        Og[idx] = 0.5f * (H[i * LDH + j] + H[j * LDH + i]);
    }
}

extern "C" void kernel_launch(void* const* d_in, const int* in_sizes, int n_in,
                              void* d_out, int out_size) {
    const float* x = (const float*)d_in[0];
    float* out = (float*)d_out;
    int nmat = in_sizes[0] / (N * N);
    size_t smem = 2 * N * LDH * sizeof(float);   // 33,280 B -> 6 blocks/SM
    spd_project_kernel<<<nmat, NT, smem>>>(x, out, nmat);
}

// round 16
// speedup vs baseline: 1.3635x; 1.0272x over previous
#include <cuda_runtime.h>
#include <math.h>

#define N 64
#define LDH 65
#define ULPF 1.1920929e-7f
#define MAXSW 960
#define NT 128
#define FULLM 0xffffffffu

__device__ float g_q[(size_t)4096 * N * N];   // Q, col-major per matrix

__device__ __forceinline__ float guard(float d){ return (fabsf(d)<1e-25f)?copysignf(1e-25f,d):d; }
__device__ __forceinline__ void gen3(float x,float y,float z,float&tau,float&v1,float&v2,float&beta){
    float ssq=y*y+z*z;
    if(ssq==0.f){tau=0.f;v1=0.f;v2=0.f;beta=x;return;}
    float nrm=sqrtf(x*x+ssq);
    beta=(x>=0.f)?-nrm:nrm;
    tau=(beta-x)/beta; float inv=1.f/(x-beta);
    v1=y*inv; v2=z*inv;
}
__device__ __forceinline__ void gen2(float x,float y,float&tau,float&v1,float&beta){
    if(y==0.f){tau=0.f;v1=0.f;beta=x;return;}
    float nrm=sqrtf(x*x+y*y);
    beta=(x>=0.f)?-nrm:nrm;
    tau=(beta-x)/beta; v1=y/(x-beta);
}

// ================= kernel 1: Hessenberg + Francis QR (Q in global) ==========
__global__ void __launch_bounds__(NT, 10)
qr_kernel(const float* __restrict__ X, float* __restrict__ OUT, int nmat)
{
    extern __shared__ float H[];     // one 64x65 plane
    __shared__ float  s_red[4];
    __shared__ float  s_v[N];
    __shared__ float4 s_mb[2];

    const int tid = threadIdx.x, warp = tid >> 5, lane = tid & 31;
    const int g = blockIdx.x;
    if (g >= nmat) return;
    const float* A = X + (size_t)g * (N * N);
    float* Og = OUT + (size_t)g * (N * N);
    float* Qg = g_q + (size_t)g * (N * N);

    for (int idx = tid; idx < N * N; idx += NT) {
        int i = idx >> 6, j = idx & 63;
        H[i * LDH + j] = A[idx];
        Qg[idx] = (i == j) ? 1.f : 0.f;   // identity (symmetric, layout-safe)
    }
    __syncthreads();

    // ---------- Hessenberg (Q accumulated in global, col-major) ----------
    for (int k = 0; k < N - 2; k++) {
        const int m = N - 1 - k;
        float t = 0.f;
        { int row = k + 2 + tid; if (row < N) { float h = H[row * LDH + k]; t = h * h; } }
        #pragma unroll
        for (int off = 16; off >= 1; off >>= 1) t += __shfl_xor_sync(FULLM, t, off);
        if (lane == 0) s_red[warp] = t;
        __syncthreads();
        const float sigma = s_red[0] + s_red[1] + s_red[2] + s_red[3];
        if (sigma > 0.f) {
            float x0 = H[(k + 1) * LDH + k];
            float mu = sqrtf(x0 * x0 + sigma);
            float v0 = (x0 <= 0.f) ? (x0 - mu) : (-sigma / (x0 + mu));
            float beta = 2.f * v0 * v0 / (sigma + v0 * v0);
            float iv0 = 1.f / v0;
            if (tid < m) s_v[tid] = (tid == 0) ? 1.f : H[(k + 1 + tid) * LDH + k] * iv0;
            __syncthreads();
            if (tid < 64) {                       // left-apply on H column j
                int j = k + tid;
                if (j < N) {
                    float w = 0.f;
                    for (int i = 0; i < m; i++) w += s_v[i] * H[(k + 1 + i) * LDH + j];
                    w *= beta;
                    for (int i = 0; i < m; i++) H[(k + 1 + i) * LDH + j] -= s_v[i] * w;
                }
            } else {                              // right-apply on Q row i (global, col-major)
                int i = tid - 64;
                float wq = 0.f;
                for (int l = 0; l < m; l++) wq += Qg[(k + 1 + l) * 64 + i] * s_v[l];
                wq *= beta;
                for (int l = 0; l < m; l++) Qg[(k + 1 + l) * 64 + i] -= wq * s_v[l];
            }
            __syncthreads();
            if (tid < N) {                        // right-apply on H row i
              int i = tid;
              float w = 0.f;
              for (int l = 0; l < m; l++) w += H[i * LDH + k + 1 + l] * s_v[l];
              w *= beta;
              for (int l = 0; l < m; l++) H[i * LDH + k + 1 + l] -= w * s_v[l];
              if (i >= k + 2) H[i * LDH + k] = 0.f;
            }
            __syncthreads();
        } else __syncthreads();
    }

    // ---------- Francis double-shift QR ----------
    {
        int its = 0, tot = 0, hi = N - 1, prev_hi = -1;
        float w[4][3];        // owner window
        float cc[2][2], pf[2];
        float tau, v1, v2, betac;
        while (true) {
            bool z1 = true, z2;
            if (lane >= 1) {
                int m1 = lane;
                float sub = fabsf(H[m1 * LDH + m1 - 1]);
                float dd = fabsf(H[(m1 - 1) * LDH + m1 - 1]) + fabsf(H[m1 * LDH + m1]);
                z1 = (sub <= ULPF * dd + 1e-30f);
                if (z1) H[m1 * LDH + m1 - 1] = 0.f;
            }
            {
                int m2 = lane + 32;
                float sub = fabsf(H[m2 * LDH + m2 - 1]);
                float dd = fabsf(H[(m2 - 1) * LDH + m2 - 1]) + fabsf(H[m2 * LDH + m2]);
                z2 = (sub <= ULPF * dd + 1e-30f);
                if (z2) H[m2 * LDH + m2 - 1] = 0.f;
            }
            unsigned lowm = __ballot_sync(FULLM, z1), highm = __ballot_sync(FULLM, z2);
            unsigned long long mask = ((unsigned long long)highm << 32) | (unsigned long long)lowm;
            __syncwarp(FULLM);
            while (hi > 0) {
                if ((mask >> hi) & 1ull) hi -= 1;
                else if ((mask >> (hi - 1)) & 1ull) hi -= 2;
                else break;
            }
            if (hi != prev_hi) { its = 0; prev_hi = hi; }
            if (hi <= 0 || tot >= MAXSW) break;
            tot++; its++;
            unsigned long long lm = mask & ((hi >= 63) ? ~0ull : ((1ull << (hi + 1)) - 1ull));
            int lo = 63 - __clzll(lm);

            float t0, d0;
            if (its % 10 == 0) {
                float s2 = fabsf(H[hi * LDH + hi - 1]) + fabsf(H[(hi - 1) * LDH + hi - 2]);
                float h11 = 0.75f * s2 + H[hi * LDH + hi];
                t0 = 2.f * h11; d0 = h11 * h11 + 0.4375f * s2 * s2;
            } else {
                t0 = H[(hi - 1) * LDH + hi - 1] + H[hi * LDH + hi];
                d0 = H[(hi - 1) * LDH + hi - 1] * H[hi * LDH + hi]
                   - H[(hi - 1) * LDH + hi] * H[hi * LDH + hi - 1];
            }
            float h00 = H[lo * LDH + lo],       h01 = H[lo * LDH + lo + 1];
            float h10 = H[(lo + 1) * LDH + lo], h11v = H[(lo + 1) * LDH + lo + 1];
            float h21 = H[(lo + 2) * LDH + lo + 1];
            gen3(h00*h00 + h01*h10 - t0*h00 + d0, h10*(h00 + h11v - t0), h21*h10, tau, v1, v2, betac);

            if (tid == 96) {
                #pragma unroll
                for (int r = 0; r < 3; r++)
                    #pragma unroll
                    for (int c = 0; c < 3; c++) w[r][c] = H[(lo + r) * LDH + lo + c];
                bool r3 = (lo + 3 <= hi);
                #pragma unroll
                for (int c = 0; c < 3; c++) w[3][c] = r3 ? H[(lo + 3) * LDH + lo + c] : 0.f;
            }
            __syncthreads();   // control reads before chase writes

            for (int k = lo; k < hi; k++) {
                bool last = (k == hi - 1);
                if (k > lo && tid < 96) { float4 mb = s_mb[k & 1]; tau = mb.x; v1 = mb.y; v2 = mb.z; }
                if (warp == 0) {                       // left: fixed column j on H
                    #pragma unroll
                    for (int rep = 0; rep < 2; rep++) {
                        int j = lane + rep * 32;
                        if (!last) {
                            if (j >= k + 3) {
                                float c0, c1;
                                if (k == lo) { c0 = H[k*LDH+j]; c1 = H[(k+1)*LDH+j]; }
                                else         { c0 = cc[rep][0]; c1 = cc[rep][1]; }
                                float c2 = H[(k + 2) * LDH + j];
                                float s0 = tau * (c0 + v1 * c1 + v2 * c2);
                                float n1 = c1 - v1 * s0, n2 = c2 - v2 * s0;
                                H[k * LDH + j] = c0 - s0;
                                if (j == k + 3) { H[(k+1)*LDH+j] = n1; H[(k+2)*LDH+j] = n2; }
                                cc[rep][0] = n1; cc[rep][1] = n2;
                            }
                        } else {
                            if (j >= k + 2) {
                                float c0, c1;
                                if (k == lo) { c0 = H[k*LDH+j]; c1 = H[(k+1)*LDH+j]; }
                                else         { c0 = cc[rep][0]; c1 = cc[rep][1]; }
                                float s0 = tau * (c0 + v1 * c1);
                                H[k * LDH + j] = c0 - s0; H[(k + 1) * LDH + j] = c1 - v1 * s0;
                            }
                        }
                    }
                } else if (warp == 1) {                // right: fixed row i on H
                    #pragma unroll
                    for (int rep = 0; rep < 2; rep++) {
                        int i = lane + rep * 32;
                        if (i < k) {
                            float c0, c1;
                            if (k == lo || i == k - 1) { c0 = H[i*LDH+k]; c1 = H[i*LDH+k+1]; }
                            else                       { c0 = cc[rep][0]; c1 = cc[rep][1]; }
                            if (!last) {
                                float c2 = H[i * LDH + k + 2];
                                float s0 = tau * (c0 + v1 * c1 + v2 * c2);
                                H[i * LDH + k] = c0 - s0;
                                cc[rep][0] = c1 - v1 * s0; cc[rep][1] = c2 - v2 * s0;
                            } else {
                                float s0 = tau * (c0 + v1 * c1);
                                H[i*LDH+k] = c0 - s0; H[i*LDH+k+1] = c1 - v1 * s0;
                            }
                        }
                    }
                } else if (warp == 2) {                // Q: fixed row i, global col-major, prefetched
                    #pragma unroll
                    for (int rep = 0; rep < 2; rep++) {
                        int i = lane + rep * 32;
                        float c0, c1;
                        if (k == lo) {
                            c0 = Qg[k * 64 + i]; c1 = Qg[(k + 1) * 64 + i];
                            if (k + 1 < hi) pf[rep] = Qg[(k + 2) * 64 + i];
                        } else { c0 = cc[rep][0]; c1 = cc[rep][1]; }
                        if (!last) {
                            float c2 = pf[rep];
                            if (k + 2 < hi) pf[rep] = Qg[(k + 3) * 64 + i];  // prefetch next fresh col
                            float s0 = tau * (c0 + v1 * c1 + v2 * c2);
                            Qg[k * 64 + i] = c0 - s0;
                            cc[rep][0] = c1 - v1 * s0; cc[rep][1] = c2 - v2 * s0;
                        } else {
                            float s0 = tau * (c0 + v1 * c1);
                            Qg[k * 64 + i] = c0 - s0; Qg[(k + 1) * 64 + i] = c1 - v1 * s0;
                        }
                    }
                } else if (lane == 0) {                // owner (tid 96)
                    if (!last) {
                        if (k > lo) H[k * LDH + k - 1] = betac;
                        #pragma unroll
                        for (int c = 0; c < 3; c++) {
                            float s0 = tau * (w[0][c] + v1 * w[1][c] + v2 * w[2][c]);
                            w[0][c] -= s0; w[1][c] -= v1 * s0; w[2][c] -= v2 * s0;
                        }
                        #pragma unroll
                        for (int r = 0; r < 4; r++) {
                            float s0 = tau * (w[r][0] + v1 * w[r][1] + v2 * w[r][2]);
                            w[r][0] -= s0; w[r][1] -= v1 * s0; w[r][2] -= v2 * s0;
                        }
                        float tn, v1n, v2n = 0.f, bn;
                        if (k + 1 == hi - 1) { gen2(w[1][0], w[2][0], tn, v1n, bn); }
                        else                 { gen3(w[1][0], w[2][0], w[3][0], tn, v1n, v2n, bn); }
                        s_mb[(k + 1) & 1] = make_float4(tn, v1n, v2n, 0.f);
                        H[k*LDH+k] = w[0][0]; H[k*LDH+k+1] = w[0][1]; H[k*LDH+k+2] = w[0][2];
                        #pragma unroll
                        for (int r = 0; r < 3; r++) { w[r][0] = w[r+1][1]; w[r][1] = w[r+1][2]; }
                        w[3][0] = 0.f; w[3][1] = 0.f;
                        tau = tn; v1 = v1n; v2 = v2n; betac = bn;
                    } else {
                        H[k * LDH + k - 1] = betac;
                        float a0 = w[0][0], a1 = w[0][1], b0 = w[1][0], b1 = w[1][1];
                        { float s0 = tau * (a0 + v1 * b0); a0 -= s0; b0 -= v1 * s0; }
                        { float s0 = tau * (a1 + v1 * b1); a1 -= s0; b1 -= v1 * s0; }
                        { float s0 = tau * (a0 + v1 * a1); a0 -= s0; a1 -= v1 * s0; }
                        { float s0 = tau * (b0 + v1 * b1); b0 -= s0; b1 -= v1 * s0; }
                        H[k*LDH+k] = a0; H[k*LDH+k+1] = a1;
                        H[(k+1)*LDH+k] = b0; H[(k+1)*LDH+k+1] = b1;
                    }
                }
                __syncthreads();
                if (tid == 96 && k + 1 < hi) {
                    int c3 = k + 3;
                    w[0][2] = H[(k + 1) * LDH + c3];
                    w[1][2] = (k + 2 <= hi) ? H[(k + 2) * LDH + c3] : 0.f;
                    w[2][2] = (k + 3 <= hi) ? H[(k + 3) * LDH + c3] : 0.f;
                    w[3][2] = (k + 4 <= hi) ? H[(k + 4) * LDH + c3] : 0.f;
                }
            }
        }
    }
    __syncthreads();

    // stage T to OUT for kernel 2
    for (int idx = tid; idx < N * N; idx += NT) {
        int i = idx >> 6, j = idx & 63;
        Og[idx] = H[i * LDH + j];
    }
}

// ================= kernel 2: f(T) block-Parlett + M = Q F Q^T ===============
__global__ void __launch_bounds__(NT, 6)
fun_kernel(float* __restrict__ OUT, int nmat)
{
    extern __shared__ float sm[];
    float* H = sm;
    float* Q = sm + N * LDH;

    __shared__ float s_red[4];
    __shared__ int   s_bs[N], s_fbi[N], s_cb[N], s_bsz[N];
    __shared__ float s_f2[N][4];
    __shared__ int   s_nb;
    __shared__ float s_amin;

    const int tid = threadIdx.x, warp = tid >> 5, lane = tid & 31;
    const int g = blockIdx.x;
    if (g >= nmat) return;
    float* Og = OUT + (size_t)g * (N * N);
    const float* Qg = g_q + (size_t)g * (N * N);

    for (int idx = tid; idx < N * N; idx += NT) {
        H[(idx >> 6) * LDH + (idx & 63)] = Og[idx];        // T (row-major staged)
        Q[(idx & 63) * LDH + (idx >> 6)] = Qg[idx];        // Q col-major -> row-major smem
    }
    __syncthreads();

    if (tid == 0) {
        int b = 0, i = 0;
        while (i < N) {
            int sz = (i < N - 1 && H[(i + 1) * LDH + i] != 0.f) ? 2 : 1;
            s_cb[b] = i; s_bsz[b] = sz;
            s_bs[i] = i; s_fbi[i] = b;
            if (sz == 2) { s_bs[i + 1] = i; s_fbi[i + 1] = b; }
            i += sz; b++;
        }
        s_nb = b;
    }
    __syncthreads();
    const int nb = s_nb;

    {
        float em = 3.4e38f;
        if (tid < nb) {
            int i = s_cb[tid];
            if (s_bsz[tid] == 1) em = fabsf(H[i * LDH + i]);
            else {
                float a=H[i*LDH+i], b=H[i*LDH+i+1], c=H[(i+1)*LDH+i], dd=H[(i+1)*LDH+i+1];
                float md=0.5f*(a-dd), disc=md*md+b*c;
                if (disc < 0.f) em = sqrtf(fmaxf(a*dd - b*c, 0.f));
                else { float sq=sqrtf(disc), m2=0.5f*(a+dd); em=fminf(fabsf(m2+sq),fabsf(m2-sq)); }
            }
        }
        #pragma unroll
        for (int off = 16; off >= 1; off >>= 1) em = fminf(em, __shfl_xor_sync(FULLM, em, off));
        if (lane == 0) s_red[warp] = em;
        __syncthreads();
        if (tid == 0) s_amin = fminf(fminf(s_red[0], s_red[1]), fminf(s_red[2], s_red[3]));
        __syncthreads();
    }

    if (tid < nb) {
        int i = s_cb[tid];
        float e = 1e-6f * s_amin;
        if (s_bsz[tid] == 1) s_f2[tid][0] = fabsf(H[i * LDH + i]) + e;
        else {
            float a=H[i*LDH+i], b=H[i*LDH+i+1], c=H[(i+1)*LDH+i], dd=H[(i+1)*LDH+i+1];
            float md=0.5f*(a-dd), disc=md*md+b*c, m2=0.5f*(a+dd);
            if (disc < 0.f) {
                float ccn = sqrtf(fmaxf(a*dd - b*c, 0.f)) + e;
                s_f2[tid][0]=ccn; s_f2[tid][1]=0.f; s_f2[tid][2]=0.f; s_f2[tid][3]=ccn;
            } else {
                float sq=sqrtf(disc), l1=m2+sq, l2=m2-sq;
                float f1=fabsf(l1)+e, f2=fabsf(l2)+e, al, be;
                if (fabsf(l1-l2) > 1e-5f*(fabsf(l1)+fabsf(l2)) + 1e-30f) {
                    float idl = 1.f/(l1-l2);
                    al=(f1-f2)*idl; be=(f2*l1-f1*l2)*idl;
                } else { al=(l1>=0.f)?1.f:-1.f; be=f1-al*l1; }
                s_f2[tid][0]=al*a+be; s_f2[tid][1]=al*b; s_f2[tid][2]=al*c; s_f2[tid][3]=al*dd+be;
            }
        }
    }
    __syncthreads();

    for (int pd = 1; pd < nb; pd++) {
        int I = tid, J = I + pd;
        if (J < nb) {
            int nI=s_bsz[I], nJ=s_bsz[J], iI=s_cb[I], iJ=s_cb[J];
            float TIJ[4], Rv[4]={0,0,0,0};
            for (int r=0;r<nI;r++) for (int c=0;c<nJ;c++) TIJ[r*2+c]=H[(iI+r)*LDH+iJ+c];
            for (int r=0;r<nI;r++) for (int c=0;c<nJ;c++) {
                float acc=0.f;
                for (int q=0;q<nI;q++) acc += s_f2[I][r*2+q]*TIJ[q*2+c];
                for (int q=0;q<nJ;q++) acc -= TIJ[r*2+q]*s_f2[J][q*2+c];
                Rv[r*2+c]=acc;
            }
            for (int K=I+1;K<J;K++) {
                int nK=s_bsz[K], iK=s_cb[K];
                for (int r=0;r<nI;r++) for (int c=0;c<nJ;c++) {
                    float acc=Rv[r*2+c];
                    for (int q=0;q<nK;q++)
                        acc += H[(iK+q)*LDH+iI+r]*H[(iK+q)*LDH+iJ+c]
                             - H[(iI+r)*LDH+iK+q]*H[(iJ+c)*LDH+iK+q];
                    Rv[r*2+c]=acc;
                }
            }
            float TII[4], TJJ[4];
            for (int r=0;r<nI;r++) for (int c=0;c<nI;c++) TII[r*2+c]=H[(iI+r)*LDH+iI+c];
            for (int r=0;r<nJ;r++) for (int c=0;c<nJ;c++) TJJ[r*2+c]=H[(iJ+r)*LDH+iJ+c];
            int n = nI * nJ;
            float K4[16], Xv[4];
            for (int c=0;c<nJ;c++) for (int r=0;r<nI;r++) {
                int row = r + nI*c;
                for (int c2=0;c2<nJ;c2++) for (int r2=0;r2<nI;r2++) {
                    int col = r2 + nI*c2;
                    float val = 0.f;
                    if (c == c2) val += TII[r*2+r2];
                    if (r == r2) val -= TJJ[c2*2+c];
                    K4[row*4+col] = val;
                }
                Xv[row] = Rv[r*2+c];
            }
            for (int p=0;p<n;p++) {
                int pv=p; float mx=fabsf(K4[p*4+p]);
                for (int q=p+1;q<n;q++){ float v=fabsf(K4[q*4+p]); if(v>mx){mx=v;pv=q;} }
                if (pv!=p){ for(int q=p;q<n;q++){float tmp=K4[p*4+q];K4[p*4+q]=K4[pv*4+q];K4[pv*4+q]=tmp;}
                            float tmp=Xv[p];Xv[p]=Xv[pv];Xv[pv]=tmp; }
                float ip = 1.f / guard(K4[p*4+p]);
                for (int q=p+1;q<n;q++) {
                    float fc = K4[q*4+p]*ip;
                    for (int q3=p+1;q3<n;q3++) K4[q*4+q3]-=fc*K4[p*4+q3];
                    Xv[q]-=fc*Xv[p];
                }
            }
            for (int p=n-1;p>=0;p--) {
                float acc=Xv[p];
                for (int q=p+1;q<n;q++) acc-=K4[p*4+q]*Xv[q];
                Xv[p]=acc/guard(K4[p*4+p]);
            }
            for (int c=0;c<nJ;c++) for (int r=0;r<nI;r++) H[(iJ+c)*LDH+iI+r]=Xv[r+nI*c];
        }
        __syncthreads();
    }

    // G = Q * F (2 threads per row)
    {
        const int r = tid & 63, half = tid >> 6;
        float acc[32];
        for (int jj = 0; jj < 32; jj++) {
            int j = half * 32 + jj;
            int bsj = s_bs[j], b = s_fbi[j];
            float a = 0.f;
            for (int i2 = 0; i2 < bsj; i2++) a += Q[r*LDH+i2] * H[j*LDH+i2];
            if (s_bsz[b] == 1) a += Q[r*LDH+j] * s_f2[b][0];
            else {
                int loc = j - bsj;
                a += Q[r*LDH+bsj] * s_f2[b][loc] + Q[r*LDH+bsj+1] * s_f2[b][2+loc];
            }
            acc[jj] = a;
        }
        __syncthreads();
        for (int jj = 0; jj < 32; jj++) H[r*LDH + half*32 + jj] = acc[jj];
    }
    __syncthreads();

    // M = G * Q^T (2 threads per row)
    {
        const int r = tid & 63, half = tid >> 6;
        float acc[32];
        for (int jj = 0; jj < 32; jj++) {
            int j = half * 32 + jj;
            float a = 0.f;
            for (int kk = 0; kk < N; kk++) a += H[r*LDH+kk] * Q[j*LDH+kk];
            acc[jj] = a;
        }
        __syncthreads();
        for (int jj = 0; jj < 32; jj++) H[r*LDH + half*32 + jj] = acc[jj];
    }
    __syncthreads();

    for (int idx = tid; idx < N * N; idx += NT) {
        int i = idx >> 6, j = idx & 63;
        Og[idx] = 0.5f * (H[i * LDH + j] + H[j * LDH + i]);
    }
}

extern "C" void kernel_launch(void* const* d_in, const int* in_sizes, int n_in,
                              void* d_out, int out_size) {
    const float* x = (const float*)d_in[0];
    float* out = (float*)d_out;
    int nmat = in_sizes[0] / (N * N);
    size_t smem1 = N * LDH * sizeof(float);       // 16,640 B -> 10 blocks/SM
    size_t smem2 = 2 * N * LDH * sizeof(float);   // 33,280 B
    qr_kernel<<<nmat, NT, smem1>>>(x, out, nmat);
    fun_kernel<<<nmat, NT, smem2>>>(out, nmat);
}